// round 1
// baseline (speedup 1.0000x reference)
#include <cuda_runtime.h>
#include <math.h>

// Problem constants (from reference)
#define NPROJS 128
#define L_DIM  1024
#define S_DIM  256
#define SPACING 4.7952f
#define MU0     0.013f

// Per-row partial terms (scratch; no allocation allowed in kernel_launch)
__device__ float g_partials[L_DIM];

// One block per row l. 256 threads, thread t handles element t of both slices.
__global__ void __launch_bounds__(S_DIM) edcc_row_kernel(
    const float* __restrict__ projs, float sigma)
{
    const int l = blockIdx.x;
    const int t = threadIdx.x;

    // Base pointers for the two used projection slices (i=127, j=29)
    const float* __restrict__ pi = projs + (size_t)127 * L_DIM * S_DIM + (size_t)l * S_DIM;
    const float* __restrict__ pj = projs + (size_t)29  * L_DIM * S_DIM + (size_t)l * S_DIM;

    // s grid: linspace((-S*sp+sp)/2, (S*sp-sp)/2, S) -> step == SPACING
    const float s_start = (-(float)S_DIM * SPACING + SPACING) * 0.5f;
    const float s = s_start + (float)t * SPACING;
    const float w = expf(sigma * s * SPACING);

    float vi = pi[t] * w;
    float vj = pj[t] * w;

    // Block reduction (8 warps), deterministic tree order
    __shared__ float sh_i[8];
    __shared__ float sh_j[8];
    const int lane = t & 31;
    const int warp = t >> 5;
    #pragma unroll
    for (int off = 16; off > 0; off >>= 1) {
        vi += __shfl_down_sync(0xFFFFFFFFu, vi, off);
        vj += __shfl_down_sync(0xFFFFFFFFu, vj, off);
    }
    if (lane == 0) { sh_i[warp] = vi; sh_j[warp] = vj; }
    __syncthreads();

    if (t == 0) {
        float Pi = 0.0f, Pj = 0.0f;
        #pragma unroll
        for (int k = 0; k < 8; k++) { Pi += sh_i[k]; Pj += sh_j[k]; }
        float den = Pi + Pj;
        float term = (den != 0.0f)
                   ? (2.0f / (float)NPROJS) * fabsf(Pi - Pj) / den
                   : 0.0f;
        g_partials[l] = term;
    }
}

// Single-block deterministic final reduce of 1024 partials.
__global__ void __launch_bounds__(256) edcc_reduce_kernel(float* __restrict__ out)
{
    const int t = threadIdx.x;
    float acc = 0.0f;
    // Fixed-order per-thread accumulation
    #pragma unroll
    for (int k = 0; k < L_DIM / 256; k++)
        acc += g_partials[t + k * 256];

    __shared__ float sh[8];
    const int lane = t & 31;
    const int warp = t >> 5;
    #pragma unroll
    for (int off = 16; off > 0; off >>= 1)
        acc += __shfl_down_sync(0xFFFFFFFFu, acc, off);
    if (lane == 0) sh[warp] = acc;
    __syncthreads();

    if (t == 0) {
        float total = 0.0f;
        #pragma unroll
        for (int k = 0; k < 8; k++) total += sh[k];
        // mean over batch B=1 -> identity
        out[0] = total;
    }
}

extern "C" void kernel_launch(void* const* d_in, const int* in_sizes, int n_in,
                              void* d_out, int out_size)
{
    const float* projs = (const float*)d_in[0];
    float* out = (float*)d_out;

    // sigma = MU0 * tan((theta[127] - theta[29]) / 2), theta_k = 2*pi*k/128
    // Computed on host in double, passed as float (matches fp32 ref within 1e-3).
    const double two_pi = 6.283185307179586;
    const double th_i = two_pi * 127.0 / 128.0;
    const double th_j = two_pi * 29.0 / 128.0;
    const float sigma = (float)((double)MU0 * tan((th_i - th_j) * 0.5));

    edcc_row_kernel<<<L_DIM, S_DIM>>>(projs, sigma);
    edcc_reduce_kernel<<<1, 256>>>(out);
}